// round 11
// baseline (speedup 1.0000x reference)
#include <cuda_runtime.h>
#include <cuda_bf16.h>
#include <cstdint>

// MaxUnpooling2DMod: out[b, y(idx), x(idx), c] += in[b,h,w,c]
//   in  [8,128,128,64] -> 2^23 floats, out [8,256,256,64] -> 2^25 floats
// decode: out_off = (b << 22) + (idx & ~63) + (lin & 63)
//
// PDL skip-chain (R8): z0,s0,z1,s1,...
//   z_b: zero slab b, no wait, trigger after stores.
//   s_b: trigger at entry (releases z_{b+1}), loads, wait (z_b completion), REDG.
// R11: max-warp scatter — 4096 blocks x 256 threads x 1 elem/thread (32768
// warps, 2x R8). Outstanding-REDG budget is per-warp, so warp count sets the
// atomic issue rate; thin threads retire fast and keep the pool topped up.

static constexpr int BLOCK = 256;

// ---- zero kernel ----
static constexpr int ZGRID      = 512;
static constexpr int ZTHREADS   = ZGRID * BLOCK;          // 131072
static constexpr int SLAB_F4    = (1 << 22) / 4;          // 1,048,576 float4
static constexpr int ZERO_PER_T = SLAB_F4 / ZTHREADS;     // 8

__global__ void __launch_bounds__(BLOCK)
zero_slab_kernel(float* __restrict__ out, int slab)
{
    const int t = blockIdx.x * BLOCK + threadIdx.x;
    float4* o4 = reinterpret_cast<float4*>(out) + (size_t)slab * SLAB_F4;
    const float4 z = make_float4(0.f, 0.f, 0.f, 0.f);
    #pragma unroll
    for (int j = 0; j < ZERO_PER_T; j++)
        o4[t + j * ZTHREADS] = z;
    asm volatile("griddepcontrol.launch_dependents;" ::: "memory");
}

// fast prologue zero (wider grid, shortest possible critical path for z0)
static constexpr int Z0GRID    = 1024;
static constexpr int Z0THREADS = Z0GRID * BLOCK;
__global__ void __launch_bounds__(BLOCK)
zero_slab0_kernel(float* __restrict__ out)
{
    const int t = blockIdx.x * BLOCK + threadIdx.x;
    float4* o4 = reinterpret_cast<float4*>(out);
    const float4 z = make_float4(0.f, 0.f, 0.f, 0.f);
    #pragma unroll
    for (int j = 0; j < SLAB_F4 / Z0THREADS; j++)         // 4
        o4[t + j * Z0THREADS] = z;
    asm volatile("griddepcontrol.launch_dependents;" ::: "memory");
}

// ---- scatter kernel: 1 elem/thread, 4096 blocks ----
static constexpr int SGRID = 4096;                        // 1,048,576 threads

__global__ void __launch_bounds__(BLOCK)
scatter_kernel(const float* __restrict__ in,
               const int*   __restrict__ idx,
               float*       __restrict__ out,
               int b)
{
    // Release z_{b+1} (disjoint slab) immediately.
    asm volatile("griddepcontrol.launch_dependents;" ::: "memory");

    const int t = blockIdx.x * BLOCK + threadIdx.x;       // 0..2^20-1
    const int e = (b << 20) + t;

    // Coalesced scalar streaming loads, issued before the wait.
    const float v = __ldcs(in  + e);
    const int   i = __ldcs(idx + e);

    // Wait for z_b (immediate predecessor) completion.
    asm volatile("griddepcontrol.wait;" ::: "memory");

    atomicAdd(out + (b << 22) + (i & ~63) + (e & 63), v);
}

extern "C" void kernel_launch(void* const* d_in, const int* in_sizes, int n_in,
                              void* d_out, int out_size)
{
    const float* in  = (const float*)d_in[0];
    const int*   idx = (const int*)d_in[1];
    float*       out = (float*)d_out;

    cudaLaunchAttribute attrs[1];
    attrs[0].id = cudaLaunchAttributeProgrammaticStreamSerialization;
    attrs[0].val.programmaticStreamSerializationAllowed = 1;

    cudaLaunchConfig_t cfg = {};
    cfg.blockDim = dim3(BLOCK, 1, 1);
    cfg.stream   = 0;

    for (int b = 0; b < 8; b++) {
        if (b == 0) {
            cfg.gridDim = dim3(Z0GRID, 1, 1);
            cfg.attrs = nullptr;  cfg.numAttrs = 0;       // no predecessor
            cudaLaunchKernelEx(&cfg, zero_slab0_kernel, out);
        } else {
            cfg.gridDim = dim3(ZGRID, 1, 1);
            cfg.attrs = attrs;    cfg.numAttrs = 1;
            cudaLaunchKernelEx(&cfg, zero_slab_kernel, out, b);
        }
        cfg.gridDim = dim3(SGRID, 1, 1);
        cfg.attrs = attrs;  cfg.numAttrs = 1;
        cudaLaunchKernelEx(&cfg, scatter_kernel, in, idx, out, b);
    }
}

// round 12
// speedup vs baseline: 1.1576x; 1.1576x over previous
#include <cuda_runtime.h>
#include <cuda_bf16.h>
#include <cstdint>

// MaxUnpooling2DMod: out[b, y(idx), x(idx), c] += in[b,h,w,c]
//   in  [8,128,128,64] -> 2^23 floats, out [8,256,256,64] -> 2^25 floats
// decode: out_off = (b << 22) + (idx & ~63) + (lin & 63)
//
// Two parallel PDL skip-chains on forked streams:
//   stream0: z0 s0 z2 s2 z4 s4 z6 s6     streamB: z1 s1 z3 s3 z5 s5 z7 s7
// True dependencies are only z_b -> s_b (disjoint slabs otherwise), so two
// chains double the number of scatter grids with atomics in flight (a single
// scatter grid does NOT saturate the L2 atomic path — R8's 120us-iso ->
// 68us-wall overlap proves concurrency raises aggregate throughput).
// Active L2 set ~4 slabs = 67MB < 126MB L2 -> atomics stay L2-hot.

static constexpr int BLOCK = 256;

// ---- zero kernel (R8 tuning): 1024 blocks x 4 float4 ----
static constexpr int ZGRID      = 1024;
static constexpr int ZTHREADS   = ZGRID * BLOCK;          // 262144
static constexpr int SLAB_F4    = (1 << 22) / 4;          // 1,048,576 float4
static constexpr int ZERO_PER_T = SLAB_F4 / ZTHREADS;     // 4

__global__ void __launch_bounds__(BLOCK)
zero_slab_kernel(float* __restrict__ out, int slab)
{
    const int t = blockIdx.x * BLOCK + threadIdx.x;
    float4* o4 = reinterpret_cast<float4*>(out) + (size_t)slab * SLAB_F4;
    const float4 z = make_float4(0.f, 0.f, 0.f, 0.f);
    #pragma unroll
    for (int j = 0; j < ZERO_PER_T; j++)
        o4[t + j * ZTHREADS] = z;
    asm volatile("griddepcontrol.launch_dependents;" ::: "memory");
}

// ---- scatter kernel (R8 tuning): 2048 blocks x 2 elems ----
static constexpr int SGRID = 2048;

__global__ void __launch_bounds__(BLOCK)
scatter_kernel(const float* __restrict__ in,
               const int*   __restrict__ idx,
               float*       __restrict__ out,
               int b)
{
    // Release the next kernel in THIS stream's chain (zero of a disjoint slab).
    asm volatile("griddepcontrol.launch_dependents;" ::: "memory");

    const int t  = blockIdx.x * BLOCK + threadIdx.x;      // 524288 threads
    const int e0 = (b << 20) + (t << 1);                  // 2 elems/thread

    const float2 v  = __ldcs(reinterpret_cast<const float2*>(in)  + (e0 >> 1));
    const int2   id = __ldcs(reinterpret_cast<const int2*>(idx)   + (e0 >> 1));

    // Wait for this stream's immediate predecessor (z_b) completion.
    asm volatile("griddepcontrol.wait;" ::: "memory");

    const int base = b << 22;
    const int c0   = e0 & 63;
    atomicAdd(out + base + (id.x & ~63) + (c0 + 0), v.x);
    atomicAdd(out + base + (id.y & ~63) + (c0 + 1), v.y);
}

extern "C" void kernel_launch(void* const* d_in, const int* in_sizes, int n_in,
                              void* d_out, int out_size)
{
    const float* in  = (const float*)d_in[0];
    const int*   idx = (const int*)d_in[1];
    float*       out = (float*)d_out;

    // One extra stream + fork/join events, created once (host objects only —
    // no device memory). The capture call takes the already-initialized path.
    static cudaStream_t sB = nullptr;
    static cudaEvent_t  evFork = nullptr, evJoin = nullptr;
    if (sB == nullptr) {
        cudaStreamCreateWithFlags(&sB, cudaStreamNonBlocking);
        cudaEventCreateWithFlags(&evFork, cudaEventDisableTiming);
        cudaEventCreateWithFlags(&evJoin, cudaEventDisableTiming);
    }

    cudaLaunchAttribute attrs[1];
    attrs[0].id = cudaLaunchAttributeProgrammaticStreamSerialization;
    attrs[0].val.programmaticStreamSerializationAllowed = 1;

    // Fork: stream B joins the capture graph.
    cudaEventRecord(evFork, 0);
    cudaStreamWaitEvent(sB, evFork, 0);

    cudaLaunchConfig_t cfg = {};
    cfg.blockDim = dim3(BLOCK, 1, 1);

    // Even batches on stream 0, odd batches on stream B; each stream runs its
    // own PDL skip-chain z,s,z,s,...
    for (int k = 0; k < 4; k++) {
        for (int lane = 0; lane < 2; lane++) {
            const int b = 2 * k + lane;
            cudaStream_t st = (lane == 0) ? (cudaStream_t)0 : sB;

            cfg.stream  = st;
            cfg.gridDim = dim3(ZGRID, 1, 1);
            cfg.attrs    = (k == 0) ? nullptr : attrs;    // first z per stream
            cfg.numAttrs = (k == 0) ? 0 : 1;
            cudaLaunchKernelEx(&cfg, zero_slab_kernel, out, b);

            cfg.gridDim = dim3(SGRID, 1, 1);
            cfg.attrs = attrs;  cfg.numAttrs = 1;
            cudaLaunchKernelEx(&cfg, scatter_kernel, in, idx, out, b);
        }
    }

    // Join: stream 0 waits for stream B's chain.
    cudaEventRecord(evJoin, sB);
    cudaStreamWaitEvent(0, evJoin, 0);
}